// round 16
// baseline (speedup 1.0000x reference)
#include <cuda_runtime.h>
#include <cuda_bf16.h>
#include <math.h>
#include <stdint.h>

// ---------------- problem constants ----------------
#define BATCH 2
#define SEQ 2048
#define DM 2048
#define PROJ 6160
#define DI 2048
#define DXB 1024
#define NH 16
#define DS 128
#define NC 16
#define CHUNKL 128
#define CONVDIM 4096
#define INTER 8192
#define NROWS (BATCH*SEQ)   // 4096

#if !defined(__CUDA_ARCH__) || defined(__CUDA_ARCH_FEAT_SM103_ALL) || defined(__CUDA_ARCH_FEAT_SM100_ALL)
#define USE_TCGEN05 1
#else
#define USE_TCGEN05 0
#endif

// ---------------- device scratch ----------------
__device__ float s_zx[(size_t)NROWS*PROJ];
__device__ float s_xBC[(size_t)NROWS*CONVDIM];
__device__ float s_dt[(size_t)NROWS*NH];
__device__ float s_dacs[(size_t)BATCH*NC*NH*128];
__device__ float s_T[(size_t)BATCH*NC*NH];
__device__ float s_states[(size_t)BATCH*NC*NH*128*128];
__device__ float s_prevT[(size_t)BATCH*NC*NH*128*128];
__device__ float s_y[(size_t)NROWS*DI];
__device__ float s_h2[(size_t)NROWS*DM];
// glu output (bf16 hi|lo), separate from g_ah/g_al to avoid racing GEMM A-operand
__device__ __nv_bfloat16 g_gh[(size_t)NROWS*INTER], g_gl[(size_t)NROWS*INTER];

// bf16 split buffers: weights transposed to [N,K], activations [M,K]
__device__ __nv_bfloat16 g_winh[(size_t)PROJ*DM],  g_winl[(size_t)PROJ*DM];
__device__ __nv_bfloat16 g_wouth[(size_t)DM*DI],   g_woutl[(size_t)DM*DI];
__device__ __nv_bfloat16 g_w13h[(size_t)2*INTER*DM], g_w13l[(size_t)2*INTER*DM];
__device__ __nv_bfloat16 g_w2h[(size_t)DM*INTER],  g_w2l[(size_t)DM*INTER];
__device__ __nv_bfloat16 g_ah[(size_t)NROWS*INTER], g_al[(size_t)NROWS*INTER];

// ---------------- small helpers ----------------
__device__ __forceinline__ float siluf(float x) { return x / (1.f + expf(-x)); }

__device__ __forceinline__ uint32_t smem_u32(const void* p) {
    uint32_t a;
    asm("{ .reg .u64 t; cvta.to.shared.u64 t, %1; cvt.u32.u64 %0, t; }" : "=r"(a) : "l"(p));
    return a;
}
__device__ __forceinline__ uint32_t elect_one() {
    uint32_t pred;
    asm volatile("{ .reg .pred p; elect.sync _|p, 0xFFFFFFFF; selp.b32 %0, 1, 0, p; }" : "=r"(pred));
    return pred;
}
#define SW128(x) ((x) ^ (((x) >> 3) & 0x70))

#define MBAR_INIT(a, c) asm volatile("mbarrier.init.shared.b64 [%0], %1;" :: "r"(a), "r"(c) : "memory")
#define MBAR_WAIT(a, ph) do { \
    uint32_t _m = (a), _p = (ph), _d; \
    asm volatile("{ .reg .pred p; mbarrier.try_wait.parity.acquire.cta.shared::cta.b64 p, [%1], %2; selp.b32 %0,1,0,p; }" \
        : "=r"(_d) : "r"(_m), "r"(_p) : "memory"); \
    if (!_d) { \
        asm volatile("{ .reg .pred P1; WL_%=: mbarrier.try_wait.parity.acquire.cta.shared::cta.b64 P1, [%0], %1, 0x989680; @P1 bra.uni WD_%=; bra.uni WL_%=; WD_%=: }" \
            :: "r"(_m), "r"(_p) : "memory"); \
    } } while (0)
#define MBAR_WAIT_CLU(a, ph) do { \
    uint32_t _m = (a), _p = (ph), _d; \
    asm volatile("{ .reg .pred p; mbarrier.try_wait.parity.acquire.cluster.shared::cta.b64 p, [%1], %2; selp.b32 %0,1,0,p; }" \
        : "=r"(_d) : "r"(_m), "r"(_p) : "memory"); \
    if (!_d) { \
        asm volatile("{ .reg .pred P1; WL_%=: mbarrier.try_wait.parity.acquire.cluster.shared::cta.b64 P1, [%0], %1, 0x989680; @P1 bra.uni WD_%=; bra.uni WL_%=; WD_%=: }" \
            :: "r"(_m), "r"(_p) : "memory"); \
    } } while (0)
#define ARRIVE_RANK0(addr) asm volatile( \
    "{ .reg .b32 r; mapa.shared::cluster.u32 r, %0, 0; mbarrier.arrive.shared::cluster.b64 _, [r]; }" \
    :: "r"(addr) : "memory")
#define CLUSTER_SYNC() do { \
    asm volatile("barrier.cluster.arrive.aligned;" ::: "memory"); \
    asm volatile("barrier.cluster.wait.aligned;" ::: "memory"); } while (0)
#define FENCE_ASYNC()     asm volatile("fence.proxy.async.shared::cta;" ::: "memory")

// cp.async 16B with runtime src-size (0 => zero-fill)
#define CP_ASYNC16(s, g, n) asm volatile( \
    "cp.async.cg.shared.global [%0], [%1], 16, %2;" :: "r"(s), "l"(g), "r"(n) : "memory")
#define CP_COMMIT() asm volatile("cp.async.commit_group;" ::: "memory")
#define CP_WAIT0()  asm volatile("cp.async.wait_group 0;" ::: "memory")

#if USE_TCGEN05
#define TC_ALLOC_CG2(sa, n)   asm volatile("tcgen05.alloc.cta_group::2.sync.aligned.shared::cta.b32 [%0], %1;" :: "r"(sa), "r"(n) : "memory")
#define TC_RELINQ_CG2()       asm volatile("tcgen05.relinquish_alloc_permit.cta_group::2.sync.aligned;")
#define TC_DEALLOC_CG2(t, n)  asm volatile("tcgen05.dealloc.cta_group::2.sync.aligned.b32 %0, %1;" :: "r"(t), "r"(n))
#define TC_COMMIT_MC2(mb, mask) asm volatile( \
    "tcgen05.commit.cta_group::2.mbarrier::arrive::one.shared::cluster.multicast::cluster.b64 [%0], %1;" \
    :: "r"(mb), "h"((uint16_t)(mask)) : "memory")
#define TC_FENCE_AFTER()  asm volatile("tcgen05.fence::after_thread_sync;" ::: "memory")
#define TC_WAIT_LD()      asm volatile("tcgen05.wait::ld.sync.aligned;" ::: "memory")

__device__ __forceinline__ void tc_mma_f16_cg2(uint32_t d, uint64_t ad, uint64_t bd,
                                               uint32_t idesc, uint32_t en) {
    asm volatile("{ .reg .pred p; setp.ne.u32 p, %5, 0;"
                 " tcgen05.mma.cta_group::2.kind::f16 [%0], %1, %2, %3, {%4,%4,%4,%4,%4,%4,%4,%4}, p; }"
                 :: "r"(d), "l"(ad), "l"(bd), "r"(idesc), "r"(0u), "r"(en) : "memory");
}
__device__ __forceinline__ uint64_t mk_desc(uint32_t addr) {
    return ((uint64_t)2 << 61) | ((uint64_t)1 << 46) | ((uint64_t)64 << 32) |
           ((uint64_t)1 << 16) | (((uint64_t)addr >> 4) & 0x3FFF);
}
#define LDTM32(r, a) asm volatile( \
    "tcgen05.ld.sync.aligned.32x32b.x32.b32 " \
    "{%0,%1,%2,%3,%4,%5,%6,%7,%8,%9,%10,%11,%12,%13,%14,%15," \
    "%16,%17,%18,%19,%20,%21,%22,%23,%24,%25,%26,%27,%28,%29,%30,%31}, [%32];" \
    : "=r"((r)[0]),"=r"((r)[1]),"=r"((r)[2]),"=r"((r)[3]),"=r"((r)[4]),"=r"((r)[5]),"=r"((r)[6]),"=r"((r)[7]), \
      "=r"((r)[8]),"=r"((r)[9]),"=r"((r)[10]),"=r"((r)[11]),"=r"((r)[12]),"=r"((r)[13]),"=r"((r)[14]),"=r"((r)[15]), \
      "=r"((r)[16]),"=r"((r)[17]),"=r"((r)[18]),"=r"((r)[19]),"=r"((r)[20]),"=r"((r)[21]),"=r"((r)[22]),"=r"((r)[23]), \
      "=r"((r)[24]),"=r"((r)[25]),"=r"((r)[26]),"=r"((r)[27]),"=r"((r)[28]),"=r"((r)[29]),"=r"((r)[30]),"=r"((r)[31]) \
    : "r"(a))
#endif

// ---------------- split-bf16 GEMM (2CTA pair, 256x512 tile, 2-stage, cp.async loads) -----
// grid.x = M/128 (cluster 2 pairs), grid.y = ceil(N/512).
// If Ghi != null: weights are (w1,w3)-column-interleaved; epilogue emits
// silu(a1)*a3 as bf16 hi/lo into Ghi/Glo [M, N/2] and skips C.
#define TG_IDESC_N256 0x10400490u    // f32 acc, bf16 a/b, M=256, N=256
#define STG_SZ 98304                 // per-stage: A_hi 16K | A_lo 16K | B_hi 32K | B_lo 32K
#define TG_SMEM (2*STG_SZ + 1024)

__global__ void __launch_bounds__(256, 1) __cluster_dims__(2, 1, 1) tgemm_kernel(
    const __nv_bfloat16* __restrict__ Ahi, const __nv_bfloat16* __restrict__ Alo,
    const __nv_bfloat16* __restrict__ Bhi, const __nv_bfloat16* __restrict__ Blo,
    const float* __restrict__ addsrc, float* __restrict__ C,
    __nv_bfloat16* __restrict__ Ghi, __nv_bfloat16* __restrict__ Glo,
    int M, int N, int K)
{
#if USE_TCGEN05
    extern __shared__ char dsm[];
    char* S = (char*)(((uintptr_t)dsm + 1023) & ~(uintptr_t)1023);
    uint32_t sb = smem_u32(S);
    const int tid = threadIdx.x, wid = tid >> 5, lid = tid & 31;
    const int rank = blockIdx.x & 1;
    const int m0 = blockIdx.x * 128;
    const int n0 = blockIdx.y * 512;
    uint32_t ctrl = sb + 2 * STG_SZ;
    uint32_t fullb[2]  = { ctrl + 8,  ctrl + 24 };
    uint32_t emptyb[2] = { ctrl + 16, ctrl + 32 };

    if (tid == 0) {
        MBAR_INIT(fullb[0], 2); MBAR_INIT(fullb[1], 2);
        MBAR_INIT(emptyb[0], 1); MBAR_INIT(emptyb[1], 1);
    }
    if (wid == 0) { TC_ALLOC_CG2(ctrl, 512); }
    __syncthreads();
    CLUSTER_SYNC();
    uint32_t tmem;
    asm volatile("ld.shared.b32 %0, [%1];" : "=r"(tmem) : "r"(ctrl));

    const int nk = K >> 6;  // chunks of 64
    for (int kc = 0; kc < nk; kc++) {
        const int s = kc & 1, r = kc >> 1;
        uint32_t stg = sb + s * STG_SZ;
        if (kc >= 2) { MBAR_WAIT(emptyb[s], (r - 1) & 1); }
        long k0 = (long)kc * 64;

        // A: own 128 rows x 128B, hi+lo (cp.async)
#pragma unroll
        for (int a = 0; a < 2; a++) {
            const __nv_bfloat16* P = a ? Alo : Ahi;
            uint32_t dst = stg + a * 16384;
#pragma unroll
            for (int it = 0; it < 4; it++) {
                int v = tid + it * 256;
                int row = v >> 3, cv = v & 7;
                const void* g = P + (size_t)(m0 + row) * K + k0 + cv * 8;
                CP_ASYNC16(dst + SW128(row * 128 + cv * 16), g, 16);
            }
        }
        // B: 256 rows = this CTA's share of the pair's 512 cols, hi+lo.
#pragma unroll
        for (int a = 0; a < 2; a++) {
            const __nv_bfloat16* P = a ? Blo : Bhi;
            uint32_t dst = stg + 32768 + a * 32768;
#pragma unroll
            for (int it = 0; it < 8; it++) {
                int v = tid + it * 256;           // 0..2047
                int row = v >> 3, cv = v & 7;
                int dd = row >> 7, j = row & 127;
                int gcol = n0 + dd * 256 + rank * 128 + j;
                int ok = (gcol < N);
                int gc = ok ? gcol : (N - 1);
                const void* g = P + (size_t)gc * K + k0 + cv * 8;
                CP_ASYNC16(dst + SW128(row * 128 + cv * 16), g, ok ? 16 : 0);
            }
        }
        CP_COMMIT();
        CP_WAIT0();
        __syncthreads();
        if (tid == 0) {
            FENCE_ASYNC();
            ARRIVE_RANK0(fullb[s]);
        }

        if (rank == 0 && wid == 0) {
            MBAR_WAIT_CLU(fullb[s], r & 1);
            if (elect_one()) {
                uint64_t dah = mk_desc(stg);
                uint64_t dal = mk_desc(stg + 16384);
                uint64_t dbh = mk_desc(stg + 32768);
                uint64_t dbl = mk_desc(stg + 65536);
                uint64_t pa[3] = { dah, dah, dal };
                uint64_t pb[3] = { dbh, dbl, dbh };
#pragma unroll
                for (int dd = 0; dd < 2; dd++) {
#pragma unroll
                    for (int p = 0; p < 3; p++) {
#pragma unroll
                        for (int k = 0; k < 4; k++) {
                            uint32_t en = !(kc == 0 && p == 0 && k == 0);
                            tc_mma_f16_cg2(tmem + dd * 256,
                                           pa[p] + k * 2,
                                           pb[p] + dd * 1024 + k * 2,
                                           TG_IDESC_N256, en);
                        }
                    }
                }
                TC_COMMIT_MC2(emptyb[s], 0x3);
            }
        }
    }

    int U = nk >> 1;
    MBAR_WAIT(emptyb[0], (U - 1) & 1);
    MBAR_WAIT(emptyb[1], (U - 1) & 1);
    TC_FENCE_AFTER();

    // epilogue: ALL 8 warps. Warp w covers lanes of subpartition (w&3)
    // (= M rows m0 + (w&3)*32..+31) and column half (w>>2): j in [jw, jw+8).
    {
        float* tile = (float*)(S + wid * (32 * 33 * 4));
        int mrow = m0 + (wid & 3) * 32;
        int jw = (wid >> 2) * 8;
#pragma unroll 1
        for (int jj = 0; jj < 8; jj++) {
            int j = jw + jj;
            uint32_t rg[32];
            LDTM32(rg, tmem + j * 32);
            TC_WAIT_LD();
            __syncwarp();
#pragma unroll
            for (int c = 0; c < 32; c++) tile[lid * 33 + c] = __uint_as_float(rg[c]);
            __syncwarp();
            if (Ghi) {
                // glu mode: columns are (a1,a3) interleaved pairs
                int p = lid & 15, rh = lid >> 4;
                long ncol = (long)(n0 >> 1) + j * 16 + p;
                if (ncol < (N >> 1)) {
#pragma unroll 4
                    for (int rr = rh * 16; rr < rh * 16 + 16; rr++) {
                        float a1 = tile[rr * 33 + 2 * p];
                        float a3 = tile[rr * 33 + 2 * p + 1];
                        float v = siluf(a1) * a3;
                        __nv_bfloat16 h = __float2bfloat16(v);
                        size_t idx = (size_t)(mrow + rr) * (N >> 1) + ncol;
                        Ghi[idx] = h;
                        Glo[idx] = __float2bfloat16(v - __bfloat162float(h));
                    }
                }
            } else {
                int n = n0 + j * 32 + lid;
                if (n < N) {
#pragma unroll 4
                    for (int rr = 0; rr < 32; rr++) {
                        float v = tile[rr * 33 + lid];
                        size_t idx = (size_t)(mrow + rr) * N + n;
                        if (addsrc) v += addsrc[idx];
                        C[idx] = v;
                    }
                }
            }
            __syncwarp();
        }
    }
    __syncthreads();
    if (wid == 0) { TC_RELINQ_CG2(); TC_DEALLOC_CG2(tmem, 512); }
    CLUSTER_SYNC();

#else
    // ============ mma.sync HMMA fallback (plain sm_103 pass) ============
    extern __shared__ char dsm[];
    char* S = (char*)(((uintptr_t)dsm + 1023) & ~(uintptr_t)1023);
    __nv_bfloat16* Ash = (__nv_bfloat16*)S;        // [128][40]
    __nv_bfloat16* Asl = Ash + 128 * 40;
    __nv_bfloat16* Bsh = Asl + 128 * 40;
    __nv_bfloat16* Bsl = Bsh + 128 * 40;
    const int tid = threadIdx.x, wid = tid >> 5, lid = tid & 31;
    const int wm = wid & 3, wn = wid >> 2;
    const int m0 = blockIdx.x * 128, n0 = blockIdx.y * 512;

    for (int nh = 0; nh < 4; nh++) {
        int n0h = n0 + nh * 128;
        float acc[64];
#pragma unroll
        for (int i = 0; i < 64; i++) acc[i] = 0.f;

        for (int kc = 0; kc < (K >> 5); kc++) {
            int k0 = kc * 32;
#pragma unroll
            for (int a = 0; a < 2; a++) {
                const __nv_bfloat16* P = a ? Alo : Ahi;
                __nv_bfloat16* dst = a ? Asl : Ash;
#pragma unroll
                for (int it = 0; it < 2; it++) {
                    int v = tid + it * 256;
                    int row = v >> 2, c8 = (v & 3) * 8;
                    uint4 d = *(const uint4*)(P + (size_t)(m0 + row) * K + k0 + c8);
                    *(uint4*)(dst + row * 40 + c8) = d;
                }
            }
#pragma unroll
            for (int a = 0; a < 2; a++) {
                const __nv_bfloat16* P = a ? Blo : Bhi;
                __nv_bfloat16* dst = a ? Bsl : Bsh;
#pragma unroll
                for (int it = 0; it < 2; it++) {
                    int v = tid + it * 256;
                    int row = v >> 2, c8 = (v & 3) * 8;
                    int n = n0h + row;
                    uint4 d = make_uint4(0, 0, 0, 0);
                    if (n < N) d = *(const uint4*)(P + (size_t)n * K + k0 + c8);
                    *(uint4*)(dst + row * 40 + c8) = d;
                }
            }
            __syncthreads();

            const __nv_bfloat16* pA[3] = { Ash, Ash, Asl };
            const __nv_bfloat16* pB[3] = { Bsh, Bsl, Bsh };
#pragma unroll
            for (int s3 = 0; s3 < 3; s3++) {
#pragma unroll
                for (int kk = 0; kk < 32; kk += 16) {
                    uint32_t af[2][4];
                    int c = kk + (lid & 3) * 2;
#pragma unroll
                    for (int i = 0; i < 2; i++) {
                        int rr = wm * 32 + i * 16 + (lid >> 2);
                        const __nv_bfloat16* base = pA[s3];
                        af[i][0] = *(const uint32_t*)(base + rr * 40 + c);
                        af[i][1] = *(const uint32_t*)(base + (rr + 8) * 40 + c);
                        af[i][2] = *(const uint32_t*)(base + rr * 40 + c + 8);
                        af[i][3] = *(const uint32_t*)(base + (rr + 8) * 40 + c + 8);
                    }
#pragma unroll
                    for (int j = 0; j < 8; j++) {
                        int n = wn * 64 + j * 8 + (lid >> 2);
                        uint32_t b0 = *(const uint32_t*)(pB[s3] + n * 40 + c);
                        uint32_t b1 = *(const uint32_t*)(pB[s3] + n * 40 + c + 8);
#pragma unroll
                        for (int i = 0; i < 2; i++) {
                            float* d = acc + (i * 8 + j) * 4;
                            asm volatile(
                                "mma.sync.aligned.m16n8k16.row.col.f32.bf16.bf16.f32 "
                                "{%0,%1,%2,%3}, {%4,%5,%6,%7}, {%8,%9}, {%0,%1,%2,%3};"
                                : "+f"(d[0]), "+f"(d[1]), "+f"(d[2]), "+f"(d[3])
                                : "r"(af[i][0]), "r"(af[i][1]), "r"(af[i][2]), "r"(af[i][3]),
                                  "r"(b0), "r"(b1));
                        }
                    }
                }
            }
            __syncthreads();
        }

#pragma unroll
        for (int i = 0; i < 2; i++) {
#pragma unroll
            for (int j = 0; j < 8; j++) {
                int row = m0 + wm * 32 + i * 16 + (lid >> 2);
                int col = n0h + wn * 64 + j * 8 + (lid & 3) * 2;   // always even
                float* d = acc + (i * 8 + j) * 4;
                if (col < N) {
                    if (Ghi) {
#pragma unroll
                        for (int rh = 0; rh < 2; rh++) {
                            float v = siluf(d[rh * 2 + 0]) * d[rh * 2 + 1];
                            __nv_bfloat16 h = __float2bfloat16(v);
                            size_t idx = (size_t)(row + 8 * rh) * (N >> 1) + (col >> 1);
                            Ghi[idx] = h;
                            Glo[idx] = __float2bfloat16(v - __bfloat162float(h));
                        }
                    } else {
#pragma unroll
                        for (int rh = 0; rh < 2; rh++) {
                            size_t idx = (size_t)(row + 8 * rh) * N + col;
                            float v0 = d[rh * 2 + 0], v1 = d[rh * 2 + 1];
                            if (addsrc) { v0 += addsrc[idx]; v1 += addsrc[idx + 1]; }
                            C[idx] = v0; C[idx + 1] = v1;
                        }
                    }
                }
            }
        }
    }
#endif
}

// ---------------- fused weight transpose+split for ALL weights (one launch) -------------
// w1/w3 rows are interleaved into w13: w1 col n -> row 2n, w3 col n -> row 2n+1.
__global__ void __launch_bounds__(256) cvt_all_kernel(
    const float* __restrict__ Win, const float* __restrict__ Wout,
    const float* __restrict__ w1, const float* __restrict__ w3, const float* __restrict__ w2,
    __nv_bfloat16* __restrict__ winh, __nv_bfloat16* __restrict__ winl,
    __nv_bfloat16* __restrict__ wouth, __nv_bfloat16* __restrict__ woutl,
    __nv_bfloat16* __restrict__ w13h, __nv_bfloat16* __restrict__ w13l,
    __nv_bfloat16* __restrict__ w2h, __nv_bfloat16* __restrict__ w2l)
{
    __shared__ float t[64][33];
    int bid = blockIdx.x;
    const float* W; __nv_bfloat16 *hi, *lo; int K, N, nx;
    int rmul = 1, radd = 0;
    if (bid < 6176)       { W = Win;  hi = winh;  lo = winl;  K = DM;    N = PROJ;  nx = 193; }
    else if (bid < 8224)  { bid -= 6176;  W = Wout; hi = wouth; lo = woutl; K = DI;  N = DM;  nx = 64; }
    else if (bid < 16416) { bid -= 8224;  W = w1; hi = w13h; lo = w13l; K = DM; N = INTER; nx = 256;
                            rmul = 2; radd = 0; }
    else if (bid < 24608) { bid -= 16416; W = w3; hi = w13h; lo = w13l; K = DM; N = INTER; nx = 256;
                            rmul = 2; radd = 1; }
    else                  { bid -= 24608; W = w2; hi = w2h; lo = w2l; K = INTER; N = DM; nx = 64; }
    int n0 = (bid % nx) * 32, k0 = (bid / nx) * 64;
    int tid = threadIdx.x;
    {
        int row = tid >> 2, c0 = (tid & 3) * 8;
        const float* src = W + (size_t)(k0 + row) * N + n0 + c0;
        if (n0 + c0 + 7 < N) {
            float4 v0 = *(const float4*)(src);
            float4 v1 = *(const float4*)(src + 4);
            t[row][c0 + 0] = v0.x; t[row][c0 + 1] = v0.y;
            t[row][c0 + 2] = v0.z; t[row][c0 + 3] = v0.w;
            t[row][c0 + 4] = v1.x; t[row][c0 + 5] = v1.y;
            t[row][c0 + 6] = v1.z; t[row][c0 + 7] = v1.w;
        } else {
#pragma unroll
            for (int j = 0; j < 8; j++) {
                int n = n0 + c0 + j;
                t[row][c0 + j] = (n < N) ? W[(size_t)(k0 + row) * N + n] : 0.f;
            }
        }
    }
    __syncthreads();
    {
        int n = tid >> 3, kk = (tid & 7) * 8;
        if (n0 + n < N) {
            __nv_bfloat16 hb[8], lb[8];
#pragma unroll
            for (int j = 0; j < 8; j++) {
                float v = t[kk + j][n];
                __nv_bfloat16 h = __float2bfloat16(v);
                hb[j] = h;
                lb[j] = __float2bfloat16(v - __bfloat162float(h));
            }
            size_t orow = (size_t)(n0 + n) * rmul + radd;
            size_t idx = orow * K + k0 + kk;
            *(uint4*)(hi + idx) = *(uint4*)hb;
            *(uint4*)(lo + idx) = *(uint4*)lb;
        }
    }
}

// ---------------- SSD micro-kernel helper ----------------
__device__ __forceinline__ void micro16(const float (*As)[128], const float (*Bs)[128],
                                        int ty, int tx, float acc[8][8]) {
#pragma unroll
    for (int k = 0; k < 16; k++) {
        float ra[8], rb[8];
#pragma unroll
        for (int i = 0; i < 8; i++) ra[i] = As[k][ty * 8 + i];
#pragma unroll
        for (int j = 0; j < 8; j++) rb[j] = Bs[k][tx * 8 + j];
#pragma unroll
        for (int i = 0; i < 8; i++)
#pragma unroll
            for (int j = 0; j < 8; j++)
                acc[i][j] = fmaf(ra[i], rb[j], acc[i][j]);
    }
}

// ---------------- rmsnorm -> bf16 hi/lo ----------------
__global__ void rmsnorm_split_kernel(const float* __restrict__ x, const float* __restrict__ w,
                                     __nv_bfloat16* __restrict__ hi, __nv_bfloat16* __restrict__ lo,
                                     int ncols)
{
    int r = blockIdx.x;
    const float* xr = x + (size_t)r * ncols;
    float ss = 0.f;
    for (int i = threadIdx.x; i < ncols; i += blockDim.x) { float v = xr[i]; ss += v * v; }
    __shared__ float red[256];
    red[threadIdx.x] = ss;
    __syncthreads();
    for (int s = 128; s > 0; s >>= 1) {
        if (threadIdx.x < s) red[threadIdx.x] += red[threadIdx.x + s];
        __syncthreads();
    }
    float scale = rsqrtf(red[0] / (float)ncols + 1e-5f);
    for (int i = threadIdx.x; i < ncols; i += blockDim.x) {
        float v = xr[i] * scale * w[i];
        __nv_bfloat16 h = __float2bfloat16(v);
        hi[(size_t)r * ncols + i] = h;
        lo[(size_t)r * ncols + i] = __float2bfloat16(v - __bfloat162float(h));
    }
}

// ---------------- gated rmsnorm -> bf16 hi/lo ----------------
__global__ void gate_rmsnorm_split_kernel(const float* __restrict__ y, const float* __restrict__ zx,
                                          const float* __restrict__ w,
                                          __nv_bfloat16* __restrict__ hi, __nv_bfloat16* __restrict__ lo)
{
    int r = blockIdx.x;
    __shared__ float buf[2048];
    __shared__ float red[256];
    float ss = 0.f;
    for (int i = threadIdx.x; i < DI; i += 256) {
        float z = zx[(size_t)r * PROJ + i];
        float v = y[(size_t)r * DI + i] * siluf(z);
        buf[i] = v;
        ss += v * v;
    }
    red[threadIdx.x] = ss;
    __syncthreads();
    for (int s = 128; s > 0; s >>= 1) {
        if (threadIdx.x < s) red[threadIdx.x] += red[threadIdx.x + s];
        __syncthreads();
    }
    float scale = rsqrtf(red[0] / (float)DI + 1e-5f);
    for (int i = threadIdx.x; i < DI; i += 256) {
        float v = buf[i] * scale * w[i];
        __nv_bfloat16 h = __float2bfloat16(v);
        hi[(size_t)r * DI + i] = h;
        lo[(size_t)r * DI + i] = __float2bfloat16(v - __bfloat162float(h));
    }
}

// ---------------- causal conv4 + silu (rolling window, 8 rows/thread) ----------------
__global__ void conv_silu_kernel(const float* __restrict__ zx, const float* __restrict__ cw,
                                 const float* __restrict__ cb, float* __restrict__ xBC)
{
    int ch = blockIdx.x * 256 + threadIdx.x;
    int r0 = blockIdx.y * 8;
    int b = r0 / SEQ, t0 = r0 % SEQ;
    float w0 = cw[ch], w1v = cw[CONVDIM + ch], w2v = cw[2 * CONVDIM + ch], w3v = cw[3 * CONVDIM + ch];
    float bias = cb[ch];
    const float* src = zx + (size_t)(b * SEQ) * PROJ + 2048 + ch;
    float h0 = (t0 >= 3) ? src[(size_t)(t0 - 3) * PROJ] : 0.f;
    float h1 = (t0 >= 2) ? src[(size_t)(t0 - 2) * PROJ] : 0.f;
    float h2 = (t0 >= 1) ? src[(size_t)(t0 - 1) * PROJ] : 0.f;
#pragma unroll
    for (int i = 0; i < 8; i++) {
        float cur = src[(size_t)(t0 + i) * PROJ];
        float acc = bias + h0 * w0 + h1 * w1v + h2 * w2v + cur * w3v;
        xBC[(size_t)(r0 + i) * CONVDIM + ch] = siluf(acc);
        h0 = h1; h1 = h2; h2 = cur;
    }
}

// ---------------- fused dt/dA + per-chunk cumsum ----------------
__global__ void dtda_scan_kernel(const float* __restrict__ zx, const float* __restrict__ dt_bias,
                                 const float* __restrict__ A_log,
                                 float* __restrict__ dt, float* __restrict__ dacs,
                                 float* __restrict__ Tsum)
{
    int bch = blockIdx.x;
    int h = bch % NH;
    int c = (bch / NH) % NC;
    int b = bch / (NH * NC);
    int row0 = b * SEQ + c * CHUNKL;
    int t = threadIdx.x;
    float x = zx[(size_t)(row0 + t) * PROJ + 6144 + h] + dt_bias[h];
    float sp = (x > 20.f) ? x : log1pf(expf(x));
    dt[(size_t)(row0 + t) * NH + h] = sp;
    __shared__ float sh[128];
    sh[t] = -sp * expf(A_log[h]);
    __syncthreads();
    for (int off = 1; off < 128; off <<= 1) {
        float v = (t >= off) ? sh[t - off] : 0.f;
        __syncthreads();
        sh[t] += v;
        __syncthreads();
    }
    dacs[(size_t)bch * 128 + t] = sh[t];
    if (t == 127) Tsum[bch] = sh[127];
}

// ---------------- chunk states ----------------
__global__ void __launch_bounds__(256) ssd_states_kernel(
    const float* __restrict__ xBC, const float* __restrict__ dt,
    const float* __restrict__ dacs, const float* __restrict__ Tsum,
    float* __restrict__ states)
{
    int bch = blockIdx.x;
    int h = bch % NH;
    int c = (bch / NH) % NC;
    int b = bch / (NH * NC);
    int kv = h >> 1;
    int row0 = b * SEQ + c * CHUNKL;
    __shared__ float Xs[16][128];
    __shared__ float Bs[16][128];
    __shared__ float wsh[128];
    int tid = threadIdx.x;
    if (tid < 128) {
        float T = Tsum[bch];
        wsh[tid] = dt[(size_t)(row0 + tid) * NH + h] * expf(T - dacs[(size_t)bch * 128 + tid]);
    }
    __syncthreads();
    int tx = tid & 15, ty = tid >> 4;
    int lr = tid >> 5, lc = (tid & 31) << 2;
    float acc[8][8] = {};
    for (int s0 = 0; s0 < 128; s0 += 16) {
#pragma unroll
        for (int i = 0; i < 2; i++) {
            int k = lr + i * 8;
            const float* base = xBC + (size_t)(row0 + s0 + k) * CONVDIM;
            float w = wsh[s0 + k];
            float4 vx = *reinterpret_cast<const float4*>(base + kv * DS + lc);
            *reinterpret_cast<float4*>(&Xs[k][lc]) =
                make_float4(vx.x * w, vx.y * w, vx.z * w, vx.w * w);
            float4 vb = *reinterpret_cast<const float4*>(base + DXB + kv * DS + lc);
            *reinterpret_cast<float4*>(&Bs[k][lc]) = vb;
        }
        __syncthreads();
        micro16(Xs, Bs, ty, tx, acc);
        __syncthreads();
    }
    float* out = states + (size_t)bch * 16384;
#pragma unroll
    for (int i = 0; i < 8; i++)
#pragma unroll
        for (int j = 0; j < 8; j++)
            out[(ty * 8 + i) * 128 + (tx * 8 + j)] = acc[i][j];
}

// ---------------- inter-chunk recurrence ----------------
__global__ void recur_kernel(const float* __restrict__ states, const float* __restrict__ Tsum,
                             float* __restrict__ prevT)
{
    int g = blockIdx.x * blockDim.x + threadIdx.x;
    if (g >= BATCH * NH * DS * DS) return;
    int p = g & 127;
    int n = (g >> 7) & 127;
    int h = (g >> 14) & 15;
    int b = g >> 18;
    float S = 0.f;
    for (int c = 0; c < NC; c++) {
        int bch = (b * NC + c) * NH + h;
        prevT[(size_t)bch * 16384 + n * 128 + p] = S;
        S = S * expf(Tsum[bch]) + states[(size_t)bch * 16384 + p * 128 + n];
    }
}

// ---------------- fused G + Y kernel ----------------
#define GY_PAD 136
#define GY_SMEM (128*GY_PAD*4 + 2*16*128*4 + 3*128*4 + 256)

__global__ void __launch_bounds__(256) ssd_y_kernel(
    const float* __restrict__ xBC, const float* __restrict__ dt,
    const float* __restrict__ dacs, const float* __restrict__ prevT,
    const float* __restrict__ Dvec, float* __restrict__ y)
{
    extern __shared__ float gy[];
    float* Gs  = gy;                       // [128][GY_PAD]
    float (*As)[128] = (float(*)[128])(gy + 128 * GY_PAD);
    float (*Bs)[128] = (float(*)[128])(gy + 128 * GY_PAD + 16 * 128);
    float* dsh = gy + 128 * GY_PAD + 2 * 16 * 128;
    float* dts = dsh + 128;
    float* eA  = dts + 128;

    int bch = blockIdx.x;
    int h = bch % NH;
    int c = (bch / NH) % NC;
    int b = bch / (NH * NC);
    int kv = h >> 1;
    int row0 = b * SEQ + c * CHUNKL;
    int tid = threadIdx.x;
    if (tid < 128) {
        float d = dacs[(size_t)bch * 128 + tid];
        dsh[tid] = d;
        eA[tid] = expf(d);
        dts[tid] = dt[(size_t)(row0 + tid) * NH + h];
    }
    __syncthreads();
    int tx = tid & 15, ty = tid >> 4;
    int ar = tid >> 2, ac = (tid & 3) << 2;
    int br = tid >> 5, bc = (tid & 31) << 2;

    {
        float acc[8][8] = {};
        for (int n0 = 0; n0 < 128; n0 += 16) {
#pragma unroll
            for (int i = 0; i < 2; i++) {
                int m = ar + i * 64;
                float4 v = *reinterpret_cast<const float4*>(
                    xBC + (size_t)(row0 + m) * CONVDIM + 2 * DXB + h * DS + n0 + ac);
                As[ac + 0][m] = v.x; As[ac + 1][m] = v.y; As[ac + 2][m] = v.z; As[ac + 3][m] = v.w;
                float4 u = *reinterpret_cast<const float4*>(
                    xBC + (size_t)(row0 + m) * CONVDIM + DXB + kv * DS + n0 + ac);
                Bs[ac + 0][m] = u.x; Bs[ac + 1][m] = u.y; Bs[ac + 2][m] = u.z; Bs[ac + 3][m] = u.w;
            }
            __syncthreads();
            micro16(As, Bs, ty, tx, acc);
            __syncthreads();
        }
#pragma unroll
        for (int i = 0; i < 8; i++) {
            int l = ty * 8 + i;
#pragma unroll
            for (int j = 0; j < 8; j++) {
                int jj = tx * 8 + j;
                Gs[l * GY_PAD + jj] = (jj <= l) ? acc[i][j] * expf(dsh[l] - dsh[jj]) : 0.f;
            }
        }
        __syncthreads();
    }

    float acc[8][8] = {};
    for (int j0 = 0; j0 < 128; j0 += 16) {
#pragma unroll
        for (int i = 0; i < 2; i++) {
            int m = ar + i * 64;
            float4 v = *reinterpret_cast<const float4*>(Gs + m * GY_PAD + j0 + ac);
            As[ac + 0][m] = v.x; As[ac + 1][m] = v.y; As[ac + 2][m] = v.z; As[ac + 3][m] = v.w;
        }
#pragma unroll
        for (int i = 0; i < 2; i++) {
            int k = br + i * 8;
            int j = j0 + k;
            float sc = dts[j];
            float4 u = *reinterpret_cast<const float4*>(
                xBC + (size_t)(row0 + j) * CONVDIM + kv * DS + bc);
            *reinterpret_cast<float4*>(&Bs[k][bc]) =
                make_float4(u.x * sc, u.y * sc, u.z * sc, u.w * sc);
        }
        __syncthreads();
        micro16(As, Bs, ty, tx, acc);
        __syncthreads();
    }

    const float* Pb = prevT + (size_t)bch * 16384;
    for (int n0 = 0; n0 < 128; n0 += 16) {
#pragma unroll
        for (int i = 0; i < 2; i++) {
            int m = ar + i * 64;
            float sc = eA[m];
            float4 v = *reinterpret_cast<const float4*>(
                xBC + (size_t)(row0 + m) * CONVDIM + 2 * DXB + h * DS + n0 + ac);
            As[ac + 0][m] = v.x * sc; As[ac + 1][m] = v.y * sc;
            As[ac + 2][m] = v.z * sc; As[ac + 3][m] = v.w * sc;
        }
#pragma unroll
        for (int i = 0; i < 2; i++) {
            int k = br + i * 8;
            float4 u = *reinterpret_cast<const float4*>(Pb + (n0 + k) * 128 + bc);
            *reinterpret_cast<float4*>(&Bs[k][bc]) = u;
        }
        __syncthreads();
        micro16(As, Bs, ty, tx, acc);
        __syncthreads();
    }

    float Dh = Dvec[h];
#pragma unroll
    for (int i = 0; i < 8; i++) {
        int l = ty * 8 + i;
        size_t row = (size_t)(row0 + l);
#pragma unroll
        for (int j = 0; j < 8; j++) {
            int p = tx * 8 + j;
            float xv = xBC[row * CONVDIM + kv * DS + p];
            y[row * DI + h * DS + p] = acc[i][j] + Dh * xv;
        }
    }
}

// ---------------- launch ----------------
extern "C" void kernel_launch(void* const* d_in, const int* in_sizes, int n_in,
                              void* d_out, int out_size)
{
    const float* hidden  = (const float*)d_in[0];
    const float* ln1_w   = (const float*)d_in[1];
    const float* W_in    = (const float*)d_in[2];
    const float* conv_w  = (const float*)d_in[3];
    const float* conv_b  = (const float*)d_in[4];
    const float* dt_bias = (const float*)d_in[5];
    const float* A_log   = (const float*)d_in[6];
    const float* Dv      = (const float*)d_in[7];
    const float* norm_w  = (const float*)d_in[8];
    const float* W_out   = (const float*)d_in[9];
    const float* ln2_w   = (const float*)d_in[10];
    const float* w1      = (const float*)d_in[11];
    const float* w3      = (const float*)d_in[12];
    const float* w2      = (const float*)d_in[13];
    float* out = (float*)d_out;

    float *p_zx, *p_xBC, *p_dt, *p_dacs, *p_T, *p_states, *p_prevT, *p_y, *p_h2;
    cudaGetSymbolAddress((void**)&p_zx, s_zx);
    cudaGetSymbolAddress((void**)&p_xBC, s_xBC);
    cudaGetSymbolAddress((void**)&p_dt, s_dt);
    cudaGetSymbolAddress((void**)&p_dacs, s_dacs);
    cudaGetSymbolAddress((void**)&p_T, s_T);
    cudaGetSymbolAddress((void**)&p_states, s_states);
    cudaGetSymbolAddress((void**)&p_prevT, s_prevT);
    cudaGetSymbolAddress((void**)&p_y, s_y);
    cudaGetSymbolAddress((void**)&p_h2, s_h2);

    __nv_bfloat16 *winh, *winl, *wouth, *woutl, *w13h, *w13l, *w2h, *w2l, *ah, *al, *gh, *gl;
    cudaGetSymbolAddress((void**)&winh, g_winh);   cudaGetSymbolAddress((void**)&winl, g_winl);
    cudaGetSymbolAddress((void**)&wouth, g_wouth); cudaGetSymbolAddress((void**)&woutl, g_woutl);
    cudaGetSymbolAddress((void**)&w13h, g_w13h);   cudaGetSymbolAddress((void**)&w13l, g_w13l);
    cudaGetSymbolAddress((void**)&w2h, g_w2h);     cudaGetSymbolAddress((void**)&w2l, g_w2l);
    cudaGetSymbolAddress((void**)&ah, g_ah);       cudaGetSymbolAddress((void**)&al, g_al);
    cudaGetSymbolAddress((void**)&gh, g_gh);       cudaGetSymbolAddress((void**)&gl, g_gl);

    cudaFuncSetAttribute(tgemm_kernel, cudaFuncAttributeMaxDynamicSharedMemorySize, TG_SMEM);
    cudaFuncSetAttribute(ssd_y_kernel, cudaFuncAttributeMaxDynamicSharedMemorySize, GY_SMEM);

    // 1. all weight conversions (w1/w3 column-interleaved into w13)
    cvt_all_kernel<<<32800, 256>>>(W_in, W_out, w1, w3, w2,
                                   winh, winl, wouth, woutl, w13h, w13l, w2h, w2l);
    // 2. rmsnorm (fused bf16 split)
    rmsnorm_split_kernel<<<NROWS, 256>>>(hidden, ln1_w, ah, al, DM);
    // 3. in-proj (tensor)
    tgemm_kernel<<<dim3(NROWS / 128, (PROJ + 511) / 512), 256, TG_SMEM>>>(
        ah, al, winh, winl, nullptr, p_zx, nullptr, nullptr, NROWS, PROJ, DM);
    // 4-8. conv / SSD path
    dtda_scan_kernel<<<BATCH * NC * NH, 128>>>(p_zx, dt_bias, A_log, p_dt, p_dacs, p_T);
    conv_silu_kernel<<<dim3(CONVDIM / 256, NROWS / 8), 256>>>(p_zx, conv_w, conv_b, p_xBC);
    ssd_states_kernel<<<BATCH * NC * NH, 256>>>(p_xBC, p_dt, p_dacs, p_T, p_states);
    recur_kernel<<<(BATCH * NH * DS * DS) / 256, 256>>>(p_states, p_T, p_prevT);
    ssd_y_kernel<<<BATCH * NC * NH, 256, GY_SMEM>>>(p_xBC, p_dt, p_dacs, p_prevT, Dv, p_y);
    // 9. gated rmsnorm (fused split)
    gate_rmsnorm_split_kernel<<<NROWS, 256>>>(p_y, p_zx, norm_w, ah, al);
    // 10. out-proj + residual
    tgemm_kernel<<<dim3(NROWS / 128, DM / 512), 256, TG_SMEM>>>(
        ah, al, wouth, woutl, hidden, p_h2, nullptr, nullptr, NROWS, DM, DI);
    // 11. rmsnorm 2 (fused split)
    rmsnorm_split_kernel<<<NROWS, 256>>>(p_h2, ln2_w, ah, al, DM);
    // 12. merged MLP up (w1|w3 interleaved) + fused SwiGLU -> bf16 hi/lo
    tgemm_kernel<<<dim3(NROWS / 128, (2 * INTER) / 512), 256, TG_SMEM>>>(
        ah, al, w13h, w13l, nullptr, nullptr, gh, gl, NROWS, 2 * INTER, DM);
    // 13. down-proj + residual -> out
    tgemm_kernel<<<dim3(NROWS / 128, DM / 512), 256, TG_SMEM>>>(
        gh, gl, w2h, w2l, p_h2, out, nullptr, nullptr, NROWS, DM, INTER);
}

// round 17
// speedup vs baseline: 1.0012x; 1.0012x over previous
#include <cuda_runtime.h>
#include <cuda_bf16.h>
#include <math.h>
#include <stdint.h>

// ---------------- problem constants ----------------
#define BATCH 2
#define SEQ 2048
#define DM 2048
#define PROJ 6160
#define DI 2048
#define DXB 1024
#define NH 16
#define DS 128
#define NC 16
#define CHUNKL 128
#define CONVDIM 4096
#define INTER 8192
#define NROWS (BATCH*SEQ)   // 4096

#if !defined(__CUDA_ARCH__) || defined(__CUDA_ARCH_FEAT_SM103_ALL) || defined(__CUDA_ARCH_FEAT_SM100_ALL)
#define USE_TCGEN05 1
#else
#define USE_TCGEN05 0
#endif

// ---------------- device scratch ----------------
__device__ float s_zx[(size_t)NROWS*PROJ];
__device__ float s_xBC[(size_t)NROWS*CONVDIM];
__device__ float s_dt[(size_t)NROWS*NH];
__device__ float s_dacs[(size_t)BATCH*NC*NH*128];
__device__ float s_T[(size_t)BATCH*NC*NH];
__device__ float s_states[(size_t)BATCH*NC*NH*128*128];
__device__ float s_prevT[(size_t)BATCH*NC*NH*128*128];
__device__ float s_y[(size_t)NROWS*DI];
__device__ float s_h2[(size_t)NROWS*DM];
// glu output (bf16 hi|lo), separate from g_ah/g_al to avoid racing GEMM A-operand
__device__ __nv_bfloat16 g_gh[(size_t)NROWS*INTER], g_gl[(size_t)NROWS*INTER];

// bf16 split buffers: weights transposed to [N,K], activations [M,K]
__device__ __nv_bfloat16 g_winh[(size_t)PROJ*DM],  g_winl[(size_t)PROJ*DM];
__device__ __nv_bfloat16 g_wouth[(size_t)DM*DI],   g_woutl[(size_t)DM*DI];
__device__ __nv_bfloat16 g_w13h[(size_t)2*INTER*DM], g_w13l[(size_t)2*INTER*DM];
__device__ __nv_bfloat16 g_w2h[(size_t)DM*INTER],  g_w2l[(size_t)DM*INTER];
__device__ __nv_bfloat16 g_ah[(size_t)NROWS*INTER], g_al[(size_t)NROWS*INTER];

// ---------------- small helpers ----------------
__device__ __forceinline__ float siluf(float x) { return x / (1.f + expf(-x)); }

__device__ __forceinline__ uint32_t smem_u32(const void* p) {
    uint32_t a;
    asm("{ .reg .u64 t; cvta.to.shared.u64 t, %1; cvt.u32.u64 %0, t; }" : "=r"(a) : "l"(p));
    return a;
}
__device__ __forceinline__ uint32_t elect_one() {
    uint32_t pred;
    asm volatile("{ .reg .pred p; elect.sync _|p, 0xFFFFFFFF; selp.b32 %0, 1, 0, p; }" : "=r"(pred));
    return pred;
}
#define SW128(x) ((x) ^ (((x) >> 3) & 0x70))

#define MBAR_INIT(a, c) asm volatile("mbarrier.init.shared.b64 [%0], %1;" :: "r"(a), "r"(c) : "memory")
#define MBAR_WAIT(a, ph) do { \
    uint32_t _m = (a), _p = (ph), _d; \
    asm volatile("{ .reg .pred p; mbarrier.try_wait.parity.acquire.cta.shared::cta.b64 p, [%1], %2; selp.b32 %0,1,0,p; }" \
        : "=r"(_d) : "r"(_m), "r"(_p) : "memory"); \
    if (!_d) { \
        asm volatile("{ .reg .pred P1; WL_%=: mbarrier.try_wait.parity.acquire.cta.shared::cta.b64 P1, [%0], %1, 0x989680; @P1 bra.uni WD_%=; bra.uni WL_%=; WD_%=: }" \
            :: "r"(_m), "r"(_p) : "memory"); \
    } } while (0)
#define MBAR_WAIT_CLU(a, ph) do { \
    uint32_t _m = (a), _p = (ph), _d; \
    asm volatile("{ .reg .pred p; mbarrier.try_wait.parity.acquire.cluster.shared::cta.b64 p, [%1], %2; selp.b32 %0,1,0,p; }" \
        : "=r"(_d) : "r"(_m), "r"(_p) : "memory"); \
    if (!_d) { \
        asm volatile("{ .reg .pred P1; WL_%=: mbarrier.try_wait.parity.acquire.cluster.shared::cta.b64 P1, [%0], %1, 0x989680; @P1 bra.uni WD_%=; bra.uni WL_%=; WD_%=: }" \
            :: "r"(_m), "r"(_p) : "memory"); \
    } } while (0)
#define ARRIVE_RANK0(addr) asm volatile( \
    "{ .reg .b32 r; mapa.shared::cluster.u32 r, %0, 0; mbarrier.arrive.shared::cluster.b64 _, [r]; }" \
    :: "r"(addr) : "memory")
#define CLUSTER_SYNC() do { \
    asm volatile("barrier.cluster.arrive.aligned;" ::: "memory"); \
    asm volatile("barrier.cluster.wait.aligned;" ::: "memory"); } while (0)
#define FENCE_ASYNC()     asm volatile("fence.proxy.async.shared::cta;" ::: "memory")

// cp.async 16B with runtime src-size (0 => zero-fill)
#define CP_ASYNC16(s, g, n) asm volatile( \
    "cp.async.cg.shared.global [%0], [%1], 16, %2;" :: "r"(s), "l"(g), "r"(n) : "memory")
#define CP_COMMIT() asm volatile("cp.async.commit_group;" ::: "memory")
#define CP_WAIT0()  asm volatile("cp.async.wait_group 0;" ::: "memory")

#if USE_TCGEN05
#define TC_ALLOC_CG2(sa, n)   asm volatile("tcgen05.alloc.cta_group::2.sync.aligned.shared::cta.b32 [%0], %1;" :: "r"(sa), "r"(n) : "memory")
#define TC_RELINQ_CG2()       asm volatile("tcgen05.relinquish_alloc_permit.cta_group::2.sync.aligned;")
#define TC_DEALLOC_CG2(t, n)  asm volatile("tcgen05.dealloc.cta_group::2.sync.aligned.b32 %0, %1;" :: "r"(t), "r"(n))
#define TC_COMMIT_MC2(mb, mask) asm volatile( \
    "tcgen05.commit.cta_group::2.mbarrier::arrive::one.shared::cluster.multicast::cluster.b64 [%0], %1;" \
    :: "r"(mb), "h"((uint16_t)(mask)) : "memory")
#define TC_FENCE_AFTER()  asm volatile("tcgen05.fence::after_thread_sync;" ::: "memory")
#define TC_WAIT_LD()      asm volatile("tcgen05.wait::ld.sync.aligned;" ::: "memory")

__device__ __forceinline__ void tc_mma_f16_cg2(uint32_t d, uint64_t ad, uint64_t bd,
                                               uint32_t idesc, uint32_t en) {
    asm volatile("{ .reg .pred p; setp.ne.u32 p, %5, 0;"
                 " tcgen05.mma.cta_group::2.kind::f16 [%0], %1, %2, %3, {%4,%4,%4,%4,%4,%4,%4,%4}, p; }"
                 :: "r"(d), "l"(ad), "l"(bd), "r"(idesc), "r"(0u), "r"(en) : "memory");
}
__device__ __forceinline__ uint64_t mk_desc(uint32_t addr) {
    return ((uint64_t)2 << 61) | ((uint64_t)1 << 46) | ((uint64_t)64 << 32) |
           ((uint64_t)1 << 16) | (((uint64_t)addr >> 4) & 0x3FFF);
}
#define LDTM32(r, a) asm volatile( \
    "tcgen05.ld.sync.aligned.32x32b.x32.b32 " \
    "{%0,%1,%2,%3,%4,%5,%6,%7,%8,%9,%10,%11,%12,%13,%14,%15," \
    "%16,%17,%18,%19,%20,%21,%22,%23,%24,%25,%26,%27,%28,%29,%30,%31}, [%32];" \
    : "=r"((r)[0]),"=r"((r)[1]),"=r"((r)[2]),"=r"((r)[3]),"=r"((r)[4]),"=r"((r)[5]),"=r"((r)[6]),"=r"((r)[7]), \
      "=r"((r)[8]),"=r"((r)[9]),"=r"((r)[10]),"=r"((r)[11]),"=r"((r)[12]),"=r"((r)[13]),"=r"((r)[14]),"=r"((r)[15]), \
      "=r"((r)[16]),"=r"((r)[17]),"=r"((r)[18]),"=r"((r)[19]),"=r"((r)[20]),"=r"((r)[21]),"=r"((r)[22]),"=r"((r)[23]), \
      "=r"((r)[24]),"=r"((r)[25]),"=r"((r)[26]),"=r"((r)[27]),"=r"((r)[28]),"=r"((r)[29]),"=r"((r)[30]),"=r"((r)[31]) \
    : "r"(a))
#endif

// ---------------- split-bf16 GEMM (2CTA pair, 256x512 tile, 2-stage, cp.async loads) -----
// grid.x = M/128 (cluster 2 pairs), grid.y = ceil(N/512).
// If Ghi != null: weights are (w1,w3)-column-interleaved; epilogue emits
// silu(a1)*a3 as bf16 hi/lo into Ghi/Glo [M, N/2] and skips C.
#define TG_IDESC_N256 0x10400490u    // f32 acc, bf16 a/b, M=256, N=256
#define STG_SZ 98304                 // per-stage: A_hi 16K | A_lo 16K | B_hi 32K | B_lo 32K
#define TG_SMEM (2*STG_SZ + 1024)

__global__ void __launch_bounds__(256, 1) __cluster_dims__(2, 1, 1) tgemm_kernel(
    const __nv_bfloat16* __restrict__ Ahi, const __nv_bfloat16* __restrict__ Alo,
    const __nv_bfloat16* __restrict__ Bhi, const __nv_bfloat16* __restrict__ Blo,
    const float* __restrict__ addsrc, float* __restrict__ C,
    __nv_bfloat16* __restrict__ Ghi, __nv_bfloat16* __restrict__ Glo,
    int M, int N, int K)
{
#if USE_TCGEN05
    extern __shared__ char dsm[];
    char* S = (char*)(((uintptr_t)dsm + 1023) & ~(uintptr_t)1023);
    uint32_t sb = smem_u32(S);
    const int tid = threadIdx.x, wid = tid >> 5, lid = tid & 31;
    const int rank = blockIdx.x & 1;
    const int m0 = blockIdx.x * 128;
    const int n0 = blockIdx.y * 512;
    uint32_t ctrl = sb + 2 * STG_SZ;
    uint32_t fullb[2]  = { ctrl + 8,  ctrl + 24 };
    uint32_t emptyb[2] = { ctrl + 16, ctrl + 32 };

    if (tid == 0) {
        MBAR_INIT(fullb[0], 2); MBAR_INIT(fullb[1], 2);
        MBAR_INIT(emptyb[0], 1); MBAR_INIT(emptyb[1], 1);
    }
    if (wid == 0) { TC_ALLOC_CG2(ctrl, 512); }
    __syncthreads();
    CLUSTER_SYNC();
    uint32_t tmem;
    asm volatile("ld.shared.b32 %0, [%1];" : "=r"(tmem) : "r"(ctrl));

    const int nk = K >> 6;  // chunks of 64
    for (int kc = 0; kc < nk; kc++) {
        const int s = kc & 1, r = kc >> 1;
        uint32_t stg = sb + s * STG_SZ;
        if (kc >= 2) { MBAR_WAIT(emptyb[s], (r - 1) & 1); }
        long k0 = (long)kc * 64;

        // A: own 128 rows x 128B, hi+lo (cp.async)
#pragma unroll
        for (int a = 0; a < 2; a++) {
            const __nv_bfloat16* P = a ? Alo : Ahi;
            uint32_t dst = stg + a * 16384;
#pragma unroll
            for (int it = 0; it < 4; it++) {
                int v = tid + it * 256;
                int row = v >> 3, cv = v & 7;
                const void* g = P + (size_t)(m0 + row) * K + k0 + cv * 8;
                CP_ASYNC16(dst + SW128(row * 128 + cv * 16), g, 16);
            }
        }
        // B: 256 rows = this CTA's share of the pair's 512 cols, hi+lo.
#pragma unroll
        for (int a = 0; a < 2; a++) {
            const __nv_bfloat16* P = a ? Blo : Bhi;
            uint32_t dst = stg + 32768 + a * 32768;
#pragma unroll
            for (int it = 0; it < 8; it++) {
                int v = tid + it * 256;           // 0..2047
                int row = v >> 3, cv = v & 7;
                int dd = row >> 7, j = row & 127;
                int gcol = n0 + dd * 256 + rank * 128 + j;
                int ok = (gcol < N);
                int gc = ok ? gcol : (N - 1);
                const void* g = P + (size_t)gc * K + k0 + cv * 8;
                CP_ASYNC16(dst + SW128(row * 128 + cv * 16), g, ok ? 16 : 0);
            }
        }
        CP_COMMIT();
        CP_WAIT0();
        __syncthreads();
        if (tid == 0) {
            FENCE_ASYNC();
            ARRIVE_RANK0(fullb[s]);
        }

        if (rank == 0 && wid == 0) {
            MBAR_WAIT_CLU(fullb[s], r & 1);
            if (elect_one()) {
                uint64_t dah = mk_desc(stg);
                uint64_t dal = mk_desc(stg + 16384);
                uint64_t dbh = mk_desc(stg + 32768);
                uint64_t dbl = mk_desc(stg + 65536);
                uint64_t pa[3] = { dah, dah, dal };
                uint64_t pb[3] = { dbh, dbl, dbh };
#pragma unroll
                for (int dd = 0; dd < 2; dd++) {
#pragma unroll
                    for (int p = 0; p < 3; p++) {
#pragma unroll
                        for (int k = 0; k < 4; k++) {
                            uint32_t en = !(kc == 0 && p == 0 && k == 0);
                            tc_mma_f16_cg2(tmem + dd * 256,
                                           pa[p] + k * 2,
                                           pb[p] + dd * 1024 + k * 2,
                                           TG_IDESC_N256, en);
                        }
                    }
                }
                TC_COMMIT_MC2(emptyb[s], 0x3);
            }
        }
    }

    int U = nk >> 1;
    MBAR_WAIT(emptyb[0], (U - 1) & 1);
    MBAR_WAIT(emptyb[1], (U - 1) & 1);
    TC_FENCE_AFTER();

    // epilogue: ALL 8 warps. Warp w covers lanes of subpartition (w&3)
    // (= M rows m0 + (w&3)*32..+31) and column half (w>>2): j in [jw, jw+8).
    {
        float* tile = (float*)(S + wid * (32 * 33 * 4));
        int mrow = m0 + (wid & 3) * 32;
        int jw = (wid >> 2) * 8;
#pragma unroll 1
        for (int jj = 0; jj < 8; jj++) {
            int j = jw + jj;
            uint32_t rg[32];
            LDTM32(rg, tmem + j * 32);
            TC_WAIT_LD();
            __syncwarp();
#pragma unroll
            for (int c = 0; c < 32; c++) tile[lid * 33 + c] = __uint_as_float(rg[c]);
            __syncwarp();
            if (Ghi) {
                // glu mode: columns are (a1,a3) interleaved pairs
                int p = lid & 15, rh = lid >> 4;
                long ncol = (long)(n0 >> 1) + j * 16 + p;
                if (ncol < (N >> 1)) {
#pragma unroll 4
                    for (int rr = rh * 16; rr < rh * 16 + 16; rr++) {
                        float a1 = tile[rr * 33 + 2 * p];
                        float a3 = tile[rr * 33 + 2 * p + 1];
                        float v = siluf(a1) * a3;
                        __nv_bfloat16 h = __float2bfloat16(v);
                        size_t idx = (size_t)(mrow + rr) * (N >> 1) + ncol;
                        Ghi[idx] = h;
                        Glo[idx] = __float2bfloat16(v - __bfloat162float(h));
                    }
                }
            } else {
                int n = n0 + j * 32 + lid;
                if (n < N) {
#pragma unroll 4
                    for (int rr = 0; rr < 32; rr++) {
                        float v = tile[rr * 33 + lid];
                        size_t idx = (size_t)(mrow + rr) * N + n;
                        if (addsrc) v += addsrc[idx];
                        C[idx] = v;
                    }
                }
            }
            __syncwarp();
        }
    }
    __syncthreads();
    if (wid == 0) { TC_RELINQ_CG2(); TC_DEALLOC_CG2(tmem, 512); }
    CLUSTER_SYNC();

#else
    // ============ mma.sync HMMA fallback (plain sm_103 pass) ============
    extern __shared__ char dsm[];
    char* S = (char*)(((uintptr_t)dsm + 1023) & ~(uintptr_t)1023);
    __nv_bfloat16* Ash = (__nv_bfloat16*)S;        // [128][40]
    __nv_bfloat16* Asl = Ash + 128 * 40;
    __nv_bfloat16* Bsh = Asl + 128 * 40;
    __nv_bfloat16* Bsl = Bsh + 128 * 40;
    const int tid = threadIdx.x, wid = tid >> 5, lid = tid & 31;
    const int wm = wid & 3, wn = wid >> 2;
    const int m0 = blockIdx.x * 128, n0 = blockIdx.y * 512;

    for (int nh = 0; nh < 4; nh++) {
        int n0h = n0 + nh * 128;
        float acc[64];
#pragma unroll
        for (int i = 0; i < 64; i++) acc[i] = 0.f;

        for (int kc = 0; kc < (K >> 5); kc++) {
            int k0 = kc * 32;
#pragma unroll
            for (int a = 0; a < 2; a++) {
                const __nv_bfloat16* P = a ? Alo : Ahi;
                __nv_bfloat16* dst = a ? Asl : Ash;
#pragma unroll
                for (int it = 0; it < 2; it++) {
                    int v = tid + it * 256;
                    int row = v >> 2, c8 = (v & 3) * 8;
                    uint4 d = *(const uint4*)(P + (size_t)(m0 + row) * K + k0 + c8);
                    *(uint4*)(dst + row * 40 + c8) = d;
                }
            }
#pragma unroll
            for (int a = 0; a < 2; a++) {
                const __nv_bfloat16* P = a ? Blo : Bhi;
                __nv_bfloat16* dst = a ? Bsl : Bsh;
#pragma unroll
                for (int it = 0; it < 2; it++) {
                    int v = tid + it * 256;
                    int row = v >> 2, c8 = (v & 3) * 8;
                    int n = n0h + row;
                    uint4 d = make_uint4(0, 0, 0, 0);
                    if (n < N) d = *(const uint4*)(P + (size_t)n * K + k0 + c8);
                    *(uint4*)(dst + row * 40 + c8) = d;
                }
            }
            __syncthreads();

            const __nv_bfloat16* pA[3] = { Ash, Ash, Asl };
            const __nv_bfloat16* pB[3] = { Bsh, Bsl, Bsh };
#pragma unroll
            for (int s3 = 0; s3 < 3; s3++) {
#pragma unroll
                for (int kk = 0; kk < 32; kk += 16) {
                    uint32_t af[2][4];
                    int c = kk + (lid & 3) * 2;
#pragma unroll
                    for (int i = 0; i < 2; i++) {
                        int rr = wm * 32 + i * 16 + (lid >> 2);
                        const __nv_bfloat16* base = pA[s3];
                        af[i][0] = *(const uint32_t*)(base + rr * 40 + c);
                        af[i][1] = *(const uint32_t*)(base + (rr + 8) * 40 + c);
                        af[i][2] = *(const uint32_t*)(base + rr * 40 + c + 8);
                        af[i][3] = *(const uint32_t*)(base + (rr + 8) * 40 + c + 8);
                    }
#pragma unroll
                    for (int j = 0; j < 8; j++) {
                        int n = wn * 64 + j * 8 + (lid >> 2);
                        uint32_t b0 = *(const uint32_t*)(pB[s3] + n * 40 + c);
                        uint32_t b1 = *(const uint32_t*)(pB[s3] + n * 40 + c + 8);
#pragma unroll
                        for (int i = 0; i < 2; i++) {
                            float* d = acc + (i * 8 + j) * 4;
                            asm volatile(
                                "mma.sync.aligned.m16n8k16.row.col.f32.bf16.bf16.f32 "
                                "{%0,%1,%2,%3}, {%4,%5,%6,%7}, {%8,%9}, {%0,%1,%2,%3};"
                                : "+f"(d[0]), "+f"(d[1]), "+f"(d[2]), "+f"(d[3])
                                : "r"(af[i][0]), "r"(af[i][1]), "r"(af[i][2]), "r"(af[i][3]),
                                  "r"(b0), "r"(b1));
                        }
                    }
                }
            }
            __syncthreads();
        }

#pragma unroll
        for (int i = 0; i < 2; i++) {
#pragma unroll
            for (int j = 0; j < 8; j++) {
                int row = m0 + wm * 32 + i * 16 + (lid >> 2);
                int col = n0h + wn * 64 + j * 8 + (lid & 3) * 2;   // always even
                float* d = acc + (i * 8 + j) * 4;
                if (col < N) {
                    if (Ghi) {
#pragma unroll
                        for (int rh = 0; rh < 2; rh++) {
                            float v = siluf(d[rh * 2 + 0]) * d[rh * 2 + 1];
                            __nv_bfloat16 h = __float2bfloat16(v);
                            size_t idx = (size_t)(row + 8 * rh) * (N >> 1) + (col >> 1);
                            Ghi[idx] = h;
                            Glo[idx] = __float2bfloat16(v - __bfloat162float(h));
                        }
                    } else {
#pragma unroll
                        for (int rh = 0; rh < 2; rh++) {
                            size_t idx = (size_t)(row + 8 * rh) * N + col;
                            float v0 = d[rh * 2 + 0], v1 = d[rh * 2 + 1];
                            if (addsrc) { v0 += addsrc[idx]; v1 += addsrc[idx + 1]; }
                            C[idx] = v0; C[idx + 1] = v1;
                        }
                    }
                }
            }
        }
    }
#endif
}

// ---------------- fused weight transpose+split for ALL weights (one launch) -------------
// w1/w3 rows are interleaved into w13: w1 col n -> row 2n, w3 col n -> row 2n+1.
__global__ void __launch_bounds__(256) cvt_all_kernel(
    const float* __restrict__ Win, const float* __restrict__ Wout,
    const float* __restrict__ w1, const float* __restrict__ w3, const float* __restrict__ w2,
    __nv_bfloat16* __restrict__ winh, __nv_bfloat16* __restrict__ winl,
    __nv_bfloat16* __restrict__ wouth, __nv_bfloat16* __restrict__ woutl,
    __nv_bfloat16* __restrict__ w13h, __nv_bfloat16* __restrict__ w13l,
    __nv_bfloat16* __restrict__ w2h, __nv_bfloat16* __restrict__ w2l)
{
    __shared__ float t[64][33];
    int bid = blockIdx.x;
    const float* W; __nv_bfloat16 *hi, *lo; int K, N, nx;
    int rmul = 1, radd = 0;
    if (bid < 6176)       { W = Win;  hi = winh;  lo = winl;  K = DM;    N = PROJ;  nx = 193; }
    else if (bid < 8224)  { bid -= 6176;  W = Wout; hi = wouth; lo = woutl; K = DI;  N = DM;  nx = 64; }
    else if (bid < 16416) { bid -= 8224;  W = w1; hi = w13h; lo = w13l; K = DM; N = INTER; nx = 256;
                            rmul = 2; radd = 0; }
    else if (bid < 24608) { bid -= 16416; W = w3; hi = w13h; lo = w13l; K = DM; N = INTER; nx = 256;
                            rmul = 2; radd = 1; }
    else                  { bid -= 24608; W = w2; hi = w2h; lo = w2l; K = INTER; N = DM; nx = 64; }
    int n0 = (bid % nx) * 32, k0 = (bid / nx) * 64;
    int tid = threadIdx.x;
    {
        int row = tid >> 2, c0 = (tid & 3) * 8;
        const float* src = W + (size_t)(k0 + row) * N + n0 + c0;
        if (n0 + c0 + 7 < N) {
            float4 v0 = *(const float4*)(src);
            float4 v1 = *(const float4*)(src + 4);
            t[row][c0 + 0] = v0.x; t[row][c0 + 1] = v0.y;
            t[row][c0 + 2] = v0.z; t[row][c0 + 3] = v0.w;
            t[row][c0 + 4] = v1.x; t[row][c0 + 5] = v1.y;
            t[row][c0 + 6] = v1.z; t[row][c0 + 7] = v1.w;
        } else {
#pragma unroll
            for (int j = 0; j < 8; j++) {
                int n = n0 + c0 + j;
                t[row][c0 + j] = (n < N) ? W[(size_t)(k0 + row) * N + n] : 0.f;
            }
        }
    }
    __syncthreads();
    {
        int n = tid >> 3, kk = (tid & 7) * 8;
        if (n0 + n < N) {
            __nv_bfloat16 hb[8], lb[8];
#pragma unroll
            for (int j = 0; j < 8; j++) {
                float v = t[kk + j][n];
                __nv_bfloat16 h = __float2bfloat16(v);
                hb[j] = h;
                lb[j] = __float2bfloat16(v - __bfloat162float(h));
            }
            size_t orow = (size_t)(n0 + n) * rmul + radd;
            size_t idx = orow * K + k0 + kk;
            *(uint4*)(hi + idx) = *(uint4*)hb;
            *(uint4*)(lo + idx) = *(uint4*)lb;
        }
    }
}

// ---------------- SSD micro-kernel helper ----------------
__device__ __forceinline__ void micro16(const float (*As)[128], const float (*Bs)[128],
                                        int ty, int tx, float acc[8][8]) {
#pragma unroll
    for (int k = 0; k < 16; k++) {
        float ra[8], rb[8];
#pragma unroll
        for (int i = 0; i < 8; i++) ra[i] = As[k][ty * 8 + i];
#pragma unroll
        for (int j = 0; j < 8; j++) rb[j] = Bs[k][tx * 8 + j];
#pragma unroll
        for (int i = 0; i < 8; i++)
#pragma unroll
            for (int j = 0; j < 8; j++)
                acc[i][j] = fmaf(ra[i], rb[j], acc[i][j]);
    }
}

// ---------------- rmsnorm -> bf16 hi/lo ----------------
__global__ void rmsnorm_split_kernel(const float* __restrict__ x, const float* __restrict__ w,
                                     __nv_bfloat16* __restrict__ hi, __nv_bfloat16* __restrict__ lo,
                                     int ncols)
{
    int r = blockIdx.x;
    const float* xr = x + (size_t)r * ncols;
    float ss = 0.f;
    for (int i = threadIdx.x; i < ncols; i += blockDim.x) { float v = xr[i]; ss += v * v; }
    __shared__ float red[256];
    red[threadIdx.x] = ss;
    __syncthreads();
    for (int s = 128; s > 0; s >>= 1) {
        if (threadIdx.x < s) red[threadIdx.x] += red[threadIdx.x + s];
        __syncthreads();
    }
    float scale = rsqrtf(red[0] / (float)ncols + 1e-5f);
    for (int i = threadIdx.x; i < ncols; i += blockDim.x) {
        float v = xr[i] * scale * w[i];
        __nv_bfloat16 h = __float2bfloat16(v);
        hi[(size_t)r * ncols + i] = h;
        lo[(size_t)r * ncols + i] = __float2bfloat16(v - __bfloat162float(h));
    }
}

// ---------------- gated rmsnorm -> bf16 hi/lo ----------------
__global__ void gate_rmsnorm_split_kernel(const float* __restrict__ y, const float* __restrict__ zx,
                                          const float* __restrict__ w,
                                          __nv_bfloat16* __restrict__ hi, __nv_bfloat16* __restrict__ lo)
{
    int r = blockIdx.x;
    __shared__ float buf[2048];
    __shared__ float red[256];
    float ss = 0.f;
    for (int i = threadIdx.x; i < DI; i += 256) {
        float z = zx[(size_t)r * PROJ + i];
        float v = y[(size_t)r * DI + i] * siluf(z);
        buf[i] = v;
        ss += v * v;
    }
    red[threadIdx.x] = ss;
    __syncthreads();
    for (int s = 128; s > 0; s >>= 1) {
        if (threadIdx.x < s) red[threadIdx.x] += red[threadIdx.x + s];
        __syncthreads();
    }
    float scale = rsqrtf(red[0] / (float)DI + 1e-5f);
    for (int i = threadIdx.x; i < DI; i += 256) {
        float v = buf[i] * scale * w[i];
        __nv_bfloat16 h = __float2bfloat16(v);
        hi[(size_t)r * DI + i] = h;
        lo[(size_t)r * DI + i] = __float2bfloat16(v - __bfloat162float(h));
    }
}

// ---------------- causal conv4 + silu (rolling window, 8 rows/thread) ----------------
__global__ void conv_silu_kernel(const float* __restrict__ zx, const float* __restrict__ cw,
                                 const float* __restrict__ cb, float* __restrict__ xBC)
{
    int ch = blockIdx.x * 256 + threadIdx.x;
    int r0 = blockIdx.y * 8;
    int b = r0 / SEQ, t0 = r0 % SEQ;
    float w0 = cw[ch], w1v = cw[CONVDIM + ch], w2v = cw[2 * CONVDIM + ch], w3v = cw[3 * CONVDIM + ch];
    float bias = cb[ch];
    const float* src = zx + (size_t)(b * SEQ) * PROJ + 2048 + ch;
    float h0 = (t0 >= 3) ? src[(size_t)(t0 - 3) * PROJ] : 0.f;
    float h1 = (t0 >= 2) ? src[(size_t)(t0 - 2) * PROJ] : 0.f;
    float h2 = (t0 >= 1) ? src[(size_t)(t0 - 1) * PROJ] : 0.f;
#pragma unroll
    for (int i = 0; i < 8; i++) {
        float cur = src[(size_t)(t0 + i) * PROJ];
        float acc = bias + h0 * w0 + h1 * w1v + h2 * w2v + cur * w3v;
        xBC[(size_t)(r0 + i) * CONVDIM + ch] = siluf(acc);
        h0 = h1; h1 = h2; h2 = cur;
    }
}

// ---------------- fused dt/dA + per-chunk cumsum ----------------
__global__ void dtda_scan_kernel(const float* __restrict__ zx, const float* __restrict__ dt_bias,
                                 const float* __restrict__ A_log,
                                 float* __restrict__ dt, float* __restrict__ dacs,
                                 float* __restrict__ Tsum)
{
    int bch = blockIdx.x;
    int h = bch % NH;
    int c = (bch / NH) % NC;
    int b = bch / (NH * NC);
    int row0 = b * SEQ + c * CHUNKL;
    int t = threadIdx.x;
    float x = zx[(size_t)(row0 + t) * PROJ + 6144 + h] + dt_bias[h];
    float sp = (x > 20.f) ? x : log1pf(expf(x));
    dt[(size_t)(row0 + t) * NH + h] = sp;
    __shared__ float sh[128];
    sh[t] = -sp * expf(A_log[h]);
    __syncthreads();
    for (int off = 1; off < 128; off <<= 1) {
        float v = (t >= off) ? sh[t - off] : 0.f;
        __syncthreads();
        sh[t] += v;
        __syncthreads();
    }
    dacs[(size_t)bch * 128 + t] = sh[t];
    if (t == 127) Tsum[bch] = sh[127];
}

// ---------------- chunk states ----------------
__global__ void __launch_bounds__(256) ssd_states_kernel(
    const float* __restrict__ xBC, const float* __restrict__ dt,
    const float* __restrict__ dacs, const float* __restrict__ Tsum,
    float* __restrict__ states)
{
    int bch = blockIdx.x;
    int h = bch % NH;
    int c = (bch / NH) % NC;
    int b = bch / (NH * NC);
    int kv = h >> 1;
    int row0 = b * SEQ + c * CHUNKL;
    __shared__ float Xs[16][128];
    __shared__ float Bs[16][128];
    __shared__ float wsh[128];
    int tid = threadIdx.x;
    if (tid < 128) {
        float T = Tsum[bch];
        wsh[tid] = dt[(size_t)(row0 + tid) * NH + h] * expf(T - dacs[(size_t)bch * 128 + tid]);
    }
    __syncthreads();
    int tx = tid & 15, ty = tid >> 4;
    int lr = tid >> 5, lc = (tid & 31) << 2;
    float acc[8][8] = {};
    for (int s0 = 0; s0 < 128; s0 += 16) {
#pragma unroll
        for (int i = 0; i < 2; i++) {
            int k = lr + i * 8;
            const float* base = xBC + (size_t)(row0 + s0 + k) * CONVDIM;
            float w = wsh[s0 + k];
            float4 vx = *reinterpret_cast<const float4*>(base + kv * DS + lc);
            *reinterpret_cast<float4*>(&Xs[k][lc]) =
                make_float4(vx.x * w, vx.y * w, vx.z * w, vx.w * w);
            float4 vb = *reinterpret_cast<const float4*>(base + DXB + kv * DS + lc);
            *reinterpret_cast<float4*>(&Bs[k][lc]) = vb;
        }
        __syncthreads();
        micro16(Xs, Bs, ty, tx, acc);
        __syncthreads();
    }
    float* out = states + (size_t)bch * 16384;
#pragma unroll
    for (int i = 0; i < 8; i++)
#pragma unroll
        for (int j = 0; j < 8; j++)
            out[(ty * 8 + i) * 128 + (tx * 8 + j)] = acc[i][j];
}

// ---------------- inter-chunk recurrence ----------------
__global__ void recur_kernel(const float* __restrict__ states, const float* __restrict__ Tsum,
                             float* __restrict__ prevT)
{
    int g = blockIdx.x * blockDim.x + threadIdx.x;
    if (g >= BATCH * NH * DS * DS) return;
    int p = g & 127;
    int n = (g >> 7) & 127;
    int h = (g >> 14) & 15;
    int b = g >> 18;
    float S = 0.f;
    for (int c = 0; c < NC; c++) {
        int bch = (b * NC + c) * NH + h;
        prevT[(size_t)bch * 16384 + n * 128 + p] = S;
        S = S * expf(Tsum[bch]) + states[(size_t)bch * 16384 + p * 128 + n];
    }
}

// ---------------- fused G + Y kernel ----------------
#define GY_PAD 136
#define GY_SMEM (128*GY_PAD*4 + 2*16*128*4 + 3*128*4 + 256)

__global__ void __launch_bounds__(256) ssd_y_kernel(
    const float* __restrict__ xBC, const float* __restrict__ dt,
    const float* __restrict__ dacs, const float* __restrict__ prevT,
    const float* __restrict__ Dvec, float* __restrict__ y)
{
    extern __shared__ float gy[];
    float* Gs  = gy;                       // [128][GY_PAD]
    float (*As)[128] = (float(*)[128])(gy + 128 * GY_PAD);
    float (*Bs)[128] = (float(*)[128])(gy + 128 * GY_PAD + 16 * 128);
    float* dsh = gy + 128 * GY_PAD + 2 * 16 * 128;
    float* dts = dsh + 128;
    float* eA  = dts + 128;

    int bch = blockIdx.x;
    int h = bch % NH;
    int c = (bch / NH) % NC;
    int b = bch / (NH * NC);
    int kv = h >> 1;
    int row0 = b * SEQ + c * CHUNKL;
    int tid = threadIdx.x;
    if (tid < 128) {
        float d = dacs[(size_t)bch * 128 + tid];
        dsh[tid] = d;
        eA[tid] = expf(d);
        dts[tid] = dt[(size_t)(row0 + tid) * NH + h];
    }
    __syncthreads();
    int tx = tid & 15, ty = tid >> 4;
    int ar = tid >> 2, ac = (tid & 3) << 2;
    int br = tid >> 5, bc = (tid & 31) << 2;

    {
        float acc[8][8] = {};
        for (int n0 = 0; n0 < 128; n0 += 16) {
#pragma unroll
            for (int i = 0; i < 2; i++) {
                int m = ar + i * 64;
                float4 v = *reinterpret_cast<const float4*>(
                    xBC + (size_t)(row0 + m) * CONVDIM + 2 * DXB + h * DS + n0 + ac);
                As[ac + 0][m] = v.x; As[ac + 1][m] = v.y; As[ac + 2][m] = v.z; As[ac + 3][m] = v.w;
                float4 u = *reinterpret_cast<const float4*>(
                    xBC + (size_t)(row0 + m) * CONVDIM + DXB + kv * DS + n0 + ac);
                Bs[ac + 0][m] = u.x; Bs[ac + 1][m] = u.y; Bs[ac + 2][m] = u.z; Bs[ac + 3][m] = u.w;
            }
            __syncthreads();
            micro16(As, Bs, ty, tx, acc);
            __syncthreads();
        }
#pragma unroll
        for (int i = 0; i < 8; i++) {
            int l = ty * 8 + i;
#pragma unroll
            for (int j = 0; j < 8; j++) {
                int jj = tx * 8 + j;
                Gs[l * GY_PAD + jj] = (jj <= l) ? acc[i][j] * expf(dsh[l] - dsh[jj]) : 0.f;
            }
        }
        __syncthreads();
    }

    float acc[8][8] = {};
    for (int j0 = 0; j0 < 128; j0 += 16) {
#pragma unroll
        for (int i = 0; i < 2; i++) {
            int m = ar + i * 64;
            float4 v = *reinterpret_cast<const float4*>(Gs + m * GY_PAD + j0 + ac);
            As[ac + 0][m] = v.x; As[ac + 1][m] = v.y; As[ac + 2][m] = v.z; As[ac + 3][m] = v.w;
        }
#pragma unroll
        for (int i = 0; i < 2; i++) {
            int k = br + i * 8;
            int j = j0 + k;
            float sc = dts[j];
            float4 u = *reinterpret_cast<const float4*>(
                xBC + (size_t)(row0 + j) * CONVDIM + kv * DS + bc);
            *reinterpret_cast<float4*>(&Bs[k][bc]) =
                make_float4(u.x * sc, u.y * sc, u.z * sc, u.w * sc);
        }
        __syncthreads();
        micro16(As, Bs, ty, tx, acc);
        __syncthreads();
    }

    const float* Pb = prevT + (size_t)bch * 16384;
    for (int n0 = 0; n0 < 128; n0 += 16) {
#pragma unroll
        for (int i = 0; i < 2; i++) {
            int m = ar + i * 64;
            float sc = eA[m];
            float4 v = *reinterpret_cast<const float4*>(
                xBC + (size_t)(row0 + m) * CONVDIM + 2 * DXB + h * DS + n0 + ac);
            As[ac + 0][m] = v.x * sc; As[ac + 1][m] = v.y * sc;
            As[ac + 2][m] = v.z * sc; As[ac + 3][m] = v.w * sc;
        }
#pragma unroll
        for (int i = 0; i < 2; i++) {
            int k = br + i * 8;
            float4 u = *reinterpret_cast<const float4*>(Pb + (n0 + k) * 128 + bc);
            *reinterpret_cast<float4*>(&Bs[k][bc]) = u;
        }
        __syncthreads();
        micro16(As, Bs, ty, tx, acc);
        __syncthreads();
    }

    float Dh = Dvec[h];
#pragma unroll
    for (int i = 0; i < 8; i++) {
        int l = ty * 8 + i;
        size_t row = (size_t)(row0 + l);
#pragma unroll
        for (int j = 0; j < 8; j++) {
            int p = tx * 8 + j;
            float xv = xBC[row * CONVDIM + kv * DS + p];
            y[row * DI + h * DS + p] = acc[i][j] + Dh * xv;
        }
    }
}

// ---------------- launch ----------------
extern "C" void kernel_launch(void* const* d_in, const int* in_sizes, int n_in,
                              void* d_out, int out_size)
{
    const float* hidden  = (const float*)d_in[0];
    const float* ln1_w   = (const float*)d_in[1];
    const float* W_in    = (const float*)d_in[2];
    const float* conv_w  = (const float*)d_in[3];
    const float* conv_b  = (const float*)d_in[4];
    const float* dt_bias = (const float*)d_in[5];
    const float* A_log   = (const float*)d_in[6];
    const float* Dv      = (const float*)d_in[7];
    const float* norm_w  = (const float*)d_in[8];
    const float* W_out   = (const float*)d_in[9];
    const float* ln2_w   = (const float*)d_in[10];
    const float* w1      = (const float*)d_in[11];
    const float* w3      = (const float*)d_in[12];
    const float* w2      = (const float*)d_in[13];
    float* out = (float*)d_out;

    float *p_zx, *p_xBC, *p_dt, *p_dacs, *p_T, *p_states, *p_prevT, *p_y, *p_h2;
    cudaGetSymbolAddress((void**)&p_zx, s_zx);
    cudaGetSymbolAddress((void**)&p_xBC, s_xBC);
    cudaGetSymbolAddress((void**)&p_dt, s_dt);
    cudaGetSymbolAddress((void**)&p_dacs, s_dacs);
    cudaGetSymbolAddress((void**)&p_T, s_T);
    cudaGetSymbolAddress((void**)&p_states, s_states);
    cudaGetSymbolAddress((void**)&p_prevT, s_prevT);
    cudaGetSymbolAddress((void**)&p_y, s_y);
    cudaGetSymbolAddress((void**)&p_h2, s_h2);

    __nv_bfloat16 *winh, *winl, *wouth, *woutl, *w13h, *w13l, *w2h, *w2l, *ah, *al, *gh, *gl;
    cudaGetSymbolAddress((void**)&winh, g_winh);   cudaGetSymbolAddress((void**)&winl, g_winl);
    cudaGetSymbolAddress((void**)&wouth, g_wouth); cudaGetSymbolAddress((void**)&woutl, g_woutl);
    cudaGetSymbolAddress((void**)&w13h, g_w13h);   cudaGetSymbolAddress((void**)&w13l, g_w13l);
    cudaGetSymbolAddress((void**)&w2h, g_w2h);     cudaGetSymbolAddress((void**)&w2l, g_w2l);
    cudaGetSymbolAddress((void**)&ah, g_ah);       cudaGetSymbolAddress((void**)&al, g_al);
    cudaGetSymbolAddress((void**)&gh, g_gh);       cudaGetSymbolAddress((void**)&gl, g_gl);

    cudaFuncSetAttribute(tgemm_kernel, cudaFuncAttributeMaxDynamicSharedMemorySize, TG_SMEM);
    cudaFuncSetAttribute(ssd_y_kernel, cudaFuncAttributeMaxDynamicSharedMemorySize, GY_SMEM);

    // 1. all weight conversions (w1/w3 column-interleaved into w13)
    cvt_all_kernel<<<32800, 256>>>(W_in, W_out, w1, w3, w2,
                                   winh, winl, wouth, woutl, w13h, w13l, w2h, w2l);
    // 2. rmsnorm (fused bf16 split)
    rmsnorm_split_kernel<<<NROWS, 256>>>(hidden, ln1_w, ah, al, DM);
    // 3. in-proj (tensor)
    tgemm_kernel<<<dim3(NROWS / 128, (PROJ + 511) / 512), 256, TG_SMEM>>>(
        ah, al, winh, winl, nullptr, p_zx, nullptr, nullptr, NROWS, PROJ, DM);
    // 4-8. conv / SSD path
    dtda_scan_kernel<<<BATCH * NC * NH, 128>>>(p_zx, dt_bias, A_log, p_dt, p_dacs, p_T);
    conv_silu_kernel<<<dim3(CONVDIM / 256, NROWS / 8), 256>>>(p_zx, conv_w, conv_b, p_xBC);
    ssd_states_kernel<<<BATCH * NC * NH, 256>>>(p_xBC, p_dt, p_dacs, p_T, p_states);
    recur_kernel<<<(BATCH * NH * DS * DS) / 256, 256>>>(p_states, p_T, p_prevT);
    ssd_y_kernel<<<BATCH * NC * NH, 256, GY_SMEM>>>(p_xBC, p_dt, p_dacs, p_prevT, Dv, p_y);
    // 9. gated rmsnorm (fused split)
    gate_rmsnorm_split_kernel<<<NROWS, 256>>>(p_y, p_zx, norm_w, ah, al);
    // 10. out-proj + residual
    tgemm_kernel<<<dim3(NROWS / 128, DM / 512), 256, TG_SMEM>>>(
        ah, al, wouth, woutl, hidden, p_h2, nullptr, nullptr, NROWS, DM, DI);
    // 11. rmsnorm 2 (fused split)
    rmsnorm_split_kernel<<<NROWS, 256>>>(p_h2, ln2_w, ah, al, DM);
    // 12. merged MLP up (w1|w3 interleaved) + fused SwiGLU -> bf16 hi/lo
    tgemm_kernel<<<dim3(NROWS / 128, (2 * INTER) / 512), 256, TG_SMEM>>>(
        ah, al, w13h, w13l, nullptr, nullptr, gh, gl, NROWS, 2 * INTER, DM);
    // 13. down-proj + residual -> out
    tgemm_kernel<<<dim3(NROWS / 128, DM / 512), 256, TG_SMEM>>>(
        gh, gl, w2h, w2l, p_h2, out, nullptr, nullptr, NROWS, DM, INTER);
}